// round 10
// baseline (speedup 1.0000x reference)
#include <cuda_runtime.h>
#include <cstdint>

#define NUM_NODES 500000
#define D 128
#define U 32
#define T 4
#define A 32
#define N_SRC 65536
#define B 8192
#define E 262144
#define BB 16  // batch rows per finalize block

typedef unsigned long long ull;

#define FMA_F32X2(d, a, b, c) \
    asm("fma.rn.f32x2 %0, %1, %2, %3;" : "=l"(d) : "l"(a), "l"(b), "l"(c))
#define PACK_DUP_F32X2(d, s) \
    asm("mov.b64 %0, {%1, %1};" : "=l"(d) : "f"(s))
#define PACK_F32X2(d, lo, hi) \
    asm("mov.b64 %0, {%1, %2};" : "=l"(d) : "f"(lo), "f"(hi))
#define UNPACK_F32X2(lo, hi, s) \
    asm("mov.b64 {%0, %1}, %2;" : "=f"(lo), "=f"(hi) : "l"(s))

// Scratch accumulator: agg[b][t][u]  (4 MB)
__device__ float g_agg[B * T * U];

// ---------------------------------------------------------------------------
// Kernel 1: edge aggregation (push, red.v4). At its LSU lane-op floor.
// ---------------------------------------------------------------------------
__global__ __launch_bounds__(256) void edge_agg_kernel(
    const float* __restrict__ nte_tab,
    const int* __restrict__ input_nodes,
    const int* __restrict__ edge_src,
    const int* __restrict__ edge_dst) {
    const int t   = blockIdx.y;
    const int e0  = blockIdx.x * 64 + (threadIdx.x >> 3);
    const int e1  = e0 + 32;
    const int sub = threadIdx.x & 7;

    const int src0 = __ldg(&edge_src[t * E + e0]);
    const int src1 = __ldg(&edge_src[t * E + e1]);
    const int dst0 = __ldg(&edge_dst[t * E + e0]);
    const int dst1 = __ldg(&edge_dst[t * E + e1]);
    const int n0   = __ldg(&input_nodes[src0]);
    const int n1   = __ldg(&input_nodes[src1]);

    const float4 v0 = __ldg((const float4*)nte_tab + (size_t)(n0 * T + t) * (U / 4) + sub);
    const float4 v1 = __ldg((const float4*)nte_tab + (size_t)(n1 * T + t) * (U / 4) + sub);

    float* p0 = g_agg + ((size_t)dst0 * T + t) * U + sub * 4;
    float* p1 = g_agg + ((size_t)dst1 * T + t) * U + sub * 4;
    asm volatile("red.global.add.v4.f32 [%0], {%1,%2,%3,%4};"
                 :: "l"(p0), "f"(v0.x), "f"(v0.y), "f"(v0.z), "f"(v0.w) : "memory");
    asm volatile("red.global.add.v4.f32 [%0], {%1,%2,%3,%4};"
                 :: "l"(p1), "f"(v1.x), "f"(v1.y), "f"(v1.z), "f"(v1.w) : "memory");
}

// ---------------------------------------------------------------------------
// Kernel 2: warp-autonomous finalize — ONE __syncthreads total.
// Block = 16 rows, 8 warps. Warp w: t = w&3 (stage B), rows (w>>2)*8..+7.
// Each warp computes scores for ALL 4 t of its rows (redundant, cheap),
// online softmax (no max-sub needed: |score| <= ~2.3), comb in registers,
// stage-B comb broadcast via shfl. node_emb gathers prefetched before the
// FMA loop.
// ---------------------------------------------------------------------------
__global__ __launch_bounds__(256, 3) void finalize_kernel(
    const float* __restrict__ node_emb,     // [NUM_NODES][D]
    const float* __restrict__ w,            // [T][U][D]
    const float* __restrict__ ws1,          // [T][U][A]
    const float* __restrict__ ws2,          // [T][A]
    const int*  __restrict__ out_nodes,     // [B]
    float*      __restrict__ out)           // [B][T][D]
{
    __shared__ float nte_s[BB][T * U];      // 8 KB

    const int b0   = blockIdx.x * BB;
    const int tid  = threadIdx.x;
    const int lane = tid & 31;
    const int warp = tid >> 5;
    const int t    = warp & 3;
    const int bbase = (warp >> 2) * 8;      // 8 rows per warp

    // Cooperative load of nte for the block's 16 rows (8 KB contiguous).
    {
        const float4* s4 = (const float4*)(g_agg + (size_t)b0 * T * U);
        float4* d4 = (float4*)&nte_s[0][0];
        #pragma unroll
        for (int i = tid; i < BB * T * U / 4; i += 256) d4[i] = s4[i];
    }
    __syncthreads();   // the only barrier

    // Stage A with online softmax accumulation.
    // esum[r] = sum_t exp(score), cacc[r] = sum_t exp(score)*nte[r][t][lane-as-u]
    float esum[8], cacc[8];
    #pragma unroll
    for (int r = 0; r < 8; r++) { esum[r] = 0.f; cacc[r] = 0.f; }

    #pragma unroll
    for (int t2 = 0; t2 < T; t2++) {
        float w1r[U];   // lane = a
        #pragma unroll
        for (int u = 0; u < U; u++) w1r[u] = __ldg(&ws1[(t2 * U + u) * A + lane]);
        const float w2r = __ldg(&ws2[t2 * A + lane]);

        #pragma unroll
        for (int r = 0; r < 8; r++) {
            const int row = bbase + r;
            const float4* n4 = (const float4*)&nte_s[row][t2 * U];  // broadcast
            float acc = 0.f;
            #pragma unroll
            for (int q = 0; q < U / 4; q++) {
                const float4 nv = n4[q];
                acc += nv.x * w1r[4 * q]     + nv.y * w1r[4 * q + 1] +
                       nv.z * w1r[4 * q + 2] + nv.w * w1r[4 * q + 3];
            }
            float sc = tanhf(acc) * w2r;
            #pragma unroll
            for (int o = 16; o; o >>= 1) sc += __shfl_xor_sync(0xFFFFFFFFu, sc, o);
            const float e = __expf(sc);     // safe: |sc| <= ~2.3
            esum[r] += e;
            cacc[r] += e * nte_s[row][t2 * U + lane];   // lane = u
        }
    }

    // comb[r][lane-as-u] in registers
    float cr[8];
    #pragma unroll
    for (int r = 0; r < 8; r++) cr[r] = cacc[r] / esum[r];

    // Prefetch node_emb rows (DRAM latency hides under the FMA loop).
    int nidx[8];
    #pragma unroll
    for (int r = 0; r < 8; r++) nidx[r] = __ldg(&out_nodes[b0 + bbase + r]);
    float4 nv[8];
    #pragma unroll
    for (int r = 0; r < 8; r++)
        nv[r] = __ldg((const float4*)node_emb + (size_t)nidx[r] * (D / 4) + lane);

    // Stage B: acc[r] = comb[r] @ w[t]; lane owns one float4 slice of D.
    ull acc[8][2];
    #pragma unroll
    for (int r = 0; r < 8; r++) { acc[r][0] = 0; acc[r][1] = 0; }

    const float4* wbase = (const float4*)w + (size_t)t * U * (D / 4) + lane;
    #pragma unroll
    for (int u = 0; u < U; u++) {
        const float4 wv = __ldg(&wbase[u * (D / 4)]);
        ull wlo, whi;
        PACK_F32X2(wlo, wv.x, wv.y);
        PACK_F32X2(whi, wv.z, wv.w);
        #pragma unroll
        for (int r = 0; r < 8; r++) {
            const float c = __shfl_sync(0xFFFFFFFFu, cr[r], u);
            ull c2;
            PACK_DUP_F32X2(c2, c);
            FMA_F32X2(acc[r][0], c2, wlo, acc[r][0]);
            FMA_F32X2(acc[r][1], c2, whi, acc[r][1]);
        }
    }

    // Residual + L2-normalize + store.
    #pragma unroll
    for (int r = 0; r < 8; r++) {
        const int b = b0 + bbase + r;
        float4 o;
        UNPACK_F32X2(o.x, o.y, acc[r][0]);
        UNPACK_F32X2(o.z, o.w, acc[r][1]);
        o.x += nv[r].x; o.y += nv[r].y; o.z += nv[r].z; o.w += nv[r].w;

        float ss = o.x * o.x + o.y * o.y + o.z * o.z + o.w * o.w;
        #pragma unroll
        for (int off = 16; off; off >>= 1) ss += __shfl_xor_sync(0xFFFFFFFFu, ss, off);

        const float scale = 1.f / fmaxf(sqrtf(ss), 1e-12f);
        o.x *= scale; o.y *= scale; o.z *= scale; o.w *= scale;

        ((float4*)out)[(size_t)(b * T + t) * (D / 4) + lane] = o;
    }
}

// ---------------------------------------------------------------------------
// Launch
// ---------------------------------------------------------------------------
extern "C" void kernel_launch(void* const* d_in, const int* in_sizes, int n_in,
                              void* d_out, int out_size) {
    const float* node_emb     = (const float*)d_in[0];
    const float* nte_tab      = (const float*)d_in[1];
    const float* trans_w      = (const float*)d_in[2];
    const float* trans_w_s1   = (const float*)d_in[3];
    const float* trans_w_s2   = (const float*)d_in[4];
    const int*   input_nodes  = (const int*)d_in[5];
    const int*   output_nodes = (const int*)d_in[6];
    const int*   edge_src     = (const int*)d_in[7];
    const int*   edge_dst     = (const int*)d_in[8];
    float*       out          = (float*)d_out;

    void* agg_ptr = nullptr;
    cudaGetSymbolAddress(&agg_ptr, g_agg);
    cudaMemsetAsync(agg_ptr, 0, (size_t)B * T * U * sizeof(float));

    dim3 grid_e(E / 64, T);
    edge_agg_kernel<<<grid_e, 256>>>(nte_tab, input_nodes, edge_src, edge_dst);

    finalize_kernel<<<B / BB, 256>>>(node_emb, trans_w, trans_w_s1, trans_w_s2,
                                     output_nodes, out);
}

// round 11
// speedup vs baseline: 1.1913x; 1.1913x over previous
#include <cuda_runtime.h>
#include <cstdint>

#define NUM_NODES 500000
#define D 128
#define U 32
#define T 4
#define A 32
#define N_SRC 65536
#define B 8192
#define E 262144
#define BB 8   // batch rows per finalize block

typedef unsigned long long ull;

#define FMA_F32X2(d, a, b, c) \
    asm("fma.rn.f32x2 %0, %1, %2, %3;" : "=l"(d) : "l"(a), "l"(b), "l"(c))
#define PACK_DUP_F32X2(d, s) \
    asm("mov.b64 %0, {%1, %1};" : "=l"(d) : "f"(s))
#define PACK_F32X2(d, lo, hi) \
    asm("mov.b64 %0, {%1, %2};" : "=l"(d) : "f"(lo), "f"(hi))
#define UNPACK_F32X2(lo, hi, s) \
    asm("mov.b64 {%0, %1}, %2;" : "=f"(lo), "=f"(hi) : "l"(s))

// Scratch accumulator: agg[b][t][u]  (4 MB)
__device__ float g_agg[B * T * U];

// ---------------------------------------------------------------------------
// Kernel 1: edge aggregation (push, red.v4), shfl-distributed indices.
// One warp = 32 edges. Lane e loads (src,dst,node) for edge e ONCE
// (3 memory instructions), then 8 phases: 8-lane groups handle 4 edges,
// indices shfl-broadcast, 1 gather + 1 red.v4 per phase.
// Memory instr: 19 per 32 edges (vs 80 before).
// ---------------------------------------------------------------------------
__global__ __launch_bounds__(256) void edge_agg_kernel(
    const float* __restrict__ nte_tab,
    const int* __restrict__ input_nodes,
    const int* __restrict__ edge_src,
    const int* __restrict__ edge_dst) {
    const int lane = threadIdx.x & 31;
    const int gw   = blockIdx.x * 8 + (threadIdx.x >> 5);   // global warp id
    const int base = gw * 32;                               // first edge (flat)
    const int t    = base >> 18;                            // E = 2^18

    // One edge per lane: indices loaded exactly once.
    const int src  = __ldg(&edge_src[base + lane]);
    const int dst  = __ldg(&edge_dst[base + lane]);
    const int row  = __ldg(&input_nodes[src]) * T + t;      // nte row id

    const int grp = lane >> 3;     // which of 4 edges this phase
    const int sub = lane & 7;      // float4 slot within U=32 row

    #pragma unroll
    for (int p = 0; p < 8; p++) {
        const int j    = 4 * p + grp;
        const int rowj = __shfl_sync(0xFFFFFFFFu, row, j);
        const int dstj = __shfl_sync(0xFFFFFFFFu, dst, j);

        const float4 v = __ldg((const float4*)nte_tab + (size_t)rowj * (U / 4) + sub);
        float* pdst = g_agg + ((size_t)dstj * T + t) * U + sub * 4;
        asm volatile("red.global.add.v4.f32 [%0], {%1,%2,%3,%4};"
                     :: "l"(pdst), "f"(v.x), "f"(v.y), "f"(v.z), "f"(v.w) : "memory");
    }
}

// ---------------------------------------------------------------------------
// Kernel 2: finalize. 128 threads = 4 warps, BB=8 rows. Warp w owns t=w.
// 3 barriers; softmax folded into combine (no 16-thread phase).
// ---------------------------------------------------------------------------
__global__ __launch_bounds__(128, 6) void finalize_kernel(
    const float* __restrict__ node_emb,     // [NUM_NODES][D]
    const float* __restrict__ w,            // [T][U][D]
    const float* __restrict__ ws1,          // [T][U][A]
    const float* __restrict__ ws2,          // [T][A]
    const int*  __restrict__ out_nodes,     // [B]
    float*      __restrict__ out)           // [B][T][D]
{
    __shared__ float nte_s[BB][T * U];      // 4 KB
    __shared__ float scores_s[BB][T];
    __shared__ float comb_s[BB][U];         // 1 KB

    const int b0   = blockIdx.x * BB;
    const int tid  = threadIdx.x;
    const int lane = tid & 31;
    const int t    = tid >> 5;              // warp = t

    // Load nte for BB rows (4 KB contiguous, 2 float4/thread)
    {
        const float4* s4 = (const float4*)(g_agg + (size_t)b0 * T * U);
        float4* d4 = (float4*)&nte_s[0][0];
        #pragma unroll
        for (int i = tid; i < BB * T * U / 4; i += 128) d4[i] = s4[i];
    }
    // Prefetch out_nodes for the block's rows (lane r keeps row r's index).
    const int nidx_mine = __ldg(&out_nodes[b0 + (lane & 7)]);
    __syncthreads();

    // Stage A: warp t computes scores for its t across 8 rows.
    {
        float w1r[U];
        #pragma unroll
        for (int u = 0; u < U; u++) w1r[u] = __ldg(&ws1[(t * U + u) * A + lane]);
        const float w2r = __ldg(&ws2[t * A + lane]);

        #pragma unroll
        for (int r = 0; r < BB; r++) {
            const float4* n4 = (const float4*)&nte_s[r][t * U];
            float acc = 0.f;
            #pragma unroll
            for (int q = 0; q < U / 4; q++) {
                const float4 nv = n4[q];
                acc += nv.x * w1r[4 * q]     + nv.y * w1r[4 * q + 1] +
                       nv.z * w1r[4 * q + 2] + nv.w * w1r[4 * q + 3];
            }
            float sc = tanhf(acc) * w2r;
            #pragma unroll
            for (int o = 16; o; o >>= 1) sc += __shfl_xor_sync(0xFFFFFFFFu, sc, o);
            if (lane == 0) scores_s[r][t] = sc;
        }
    }
    __syncthreads();

    // Combine with inline softmax: BB*U = 256 items, 2 per thread.
    #pragma unroll
    for (int i = tid; i < BB * U; i += 128) {
        const int bb = i >> 5, u = i & 31;
        const float s0 = scores_s[bb][0], s1 = scores_s[bb][1];
        const float s2 = scores_s[bb][2], s3 = scores_s[bb][3];
        const float m  = fmaxf(fmaxf(s0, s1), fmaxf(s2, s3));
        const float e0 = __expf(s0 - m), e1 = __expf(s1 - m);
        const float e2 = __expf(s2 - m), e3 = __expf(s3 - m);
        const float inv = 1.f / (e0 + e1 + e2 + e3);
        comb_s[bb][u] = (e0 * nte_s[bb][0 * U + u] + e1 * nte_s[bb][1 * U + u] +
                         e2 * nte_s[bb][2 * U + u] + e3 * nte_s[bb][3 * U + u]) * inv;
    }
    __syncthreads();

    // Stage B: warp t: acc[r] = comb[r] @ w[t] for 8 rows; f32x2 FMAs.
    ull acc[BB][2];
    #pragma unroll
    for (int r = 0; r < BB; r++) { acc[r][0] = 0; acc[r][1] = 0; }

    const float4* wbase = (const float4*)w + (size_t)t * U * (D / 4) + lane;
    #pragma unroll
    for (int uc = 0; uc < U; uc += 4) {
        ull wlo[4], whi[4];
        #pragma unroll
        for (int j = 0; j < 4; j++) {
            const float4 wv = __ldg(&wbase[(uc + j) * (D / 4)]);
            PACK_F32X2(wlo[j], wv.x, wv.y);
            PACK_F32X2(whi[j], wv.z, wv.w);
        }
        #pragma unroll
        for (int r = 0; r < BB; r++) {
            const float4 cb = ((const float4*)&comb_s[r][0])[uc >> 2];  // LDS.128
            ull c2;
            PACK_DUP_F32X2(c2, cb.x);
            FMA_F32X2(acc[r][0], c2, wlo[0], acc[r][0]);
            FMA_F32X2(acc[r][1], c2, whi[0], acc[r][1]);
            PACK_DUP_F32X2(c2, cb.y);
            FMA_F32X2(acc[r][0], c2, wlo[1], acc[r][0]);
            FMA_F32X2(acc[r][1], c2, whi[1], acc[r][1]);
            PACK_DUP_F32X2(c2, cb.z);
            FMA_F32X2(acc[r][0], c2, wlo[2], acc[r][0]);
            FMA_F32X2(acc[r][1], c2, whi[2], acc[r][1]);
            PACK_DUP_F32X2(c2, cb.w);
            FMA_F32X2(acc[r][0], c2, wlo[3], acc[r][0]);
            FMA_F32X2(acc[r][1], c2, whi[3], acc[r][1]);
        }
    }

    // Residual + normalize + store.
    #pragma unroll
    for (int r = 0; r < BB; r++) {
        const int b    = b0 + r;
        const int nidx = __shfl_sync(0xFFFFFFFFu, nidx_mine, r);

        float4 o;
        UNPACK_F32X2(o.x, o.y, acc[r][0]);
        UNPACK_F32X2(o.z, o.w, acc[r][1]);

        const float4 nv = __ldg((const float4*)node_emb + (size_t)nidx * (D / 4) + lane);
        o.x += nv.x; o.y += nv.y; o.z += nv.z; o.w += nv.w;

        float ss = o.x * o.x + o.y * o.y + o.z * o.z + o.w * o.w;
        #pragma unroll
        for (int off = 16; off; off >>= 1) ss += __shfl_xor_sync(0xFFFFFFFFu, ss, off);

        const float scale = 1.f / fmaxf(sqrtf(ss), 1e-12f);
        o.x *= scale; o.y *= scale; o.z *= scale; o.w *= scale;

        ((float4*)out)[(size_t)(b * T + t) * (D / 4) + lane] = o;
    }
}

// ---------------------------------------------------------------------------
// Launch
// ---------------------------------------------------------------------------
extern "C" void kernel_launch(void* const* d_in, const int* in_sizes, int n_in,
                              void* d_out, int out_size) {
    const float* node_emb     = (const float*)d_in[0];
    const float* nte_tab      = (const float*)d_in[1];
    const float* trans_w      = (const float*)d_in[2];
    const float* trans_w_s1   = (const float*)d_in[3];
    const float* trans_w_s2   = (const float*)d_in[4];
    const int*   input_nodes  = (const int*)d_in[5];
    const int*   output_nodes = (const int*)d_in[6];
    const int*   edge_src     = (const int*)d_in[7];
    const int*   edge_dst     = (const int*)d_in[8];
    float*       out          = (float*)d_out;

    void* agg_ptr = nullptr;
    cudaGetSymbolAddress(&agg_ptr, g_agg);
    cudaMemsetAsync(agg_ptr, 0, (size_t)B * T * U * sizeof(float));

    // T*E edges, 256 edges per block (8 warps x 32)
    edge_agg_kernel<<<(T * E) / 256, 256>>>(nte_tab, input_nodes, edge_src, edge_dst);

    finalize_kernel<<<B / BB, 128>>>(node_emb, trans_w, trans_w_s1, trans_w_s2,
                                     output_nodes, out);
}

// round 12
// speedup vs baseline: 1.2798x; 1.0743x over previous
#include <cuda_runtime.h>
#include <cstdint>

#define NUM_NODES 500000
#define D 128
#define U 32
#define T 4
#define A 32
#define N_SRC 65536
#define B 8192
#define E 262144
#define BB 16  // batch rows per finalize block

typedef unsigned long long ull;

#define FMA_F32X2(d, a, b, c) \
    asm("fma.rn.f32x2 %0, %1, %2, %3;" : "=l"(d) : "l"(a), "l"(b), "l"(c))
#define PACK_DUP_F32X2(d, s) \
    asm("mov.b64 %0, {%1, %1};" : "=l"(d) : "f"(s))
#define PACK_F32X2(d, lo, hi) \
    asm("mov.b64 %0, {%1, %2};" : "=l"(d) : "f"(lo), "f"(hi))
#define UNPACK_F32X2(lo, hi, s) \
    asm("mov.b64 {%0, %1}, %2;" : "=f"(lo), "=f"(hi) : "l"(s))

// Scratch accumulator: agg[b][t][u]  (4 MB)
__device__ float g_agg[B * T * U];

// ---------------------------------------------------------------------------
// Kernel 1: edge aggregation (push, red.v4), shfl-distributed indices.
// One warp = 32 edges. Lane e loads (src,dst,node) for edge e ONCE,
// then 8 phases: 8-lane groups handle 4 edges, indices shfl-broadcast,
// 1 gather + 1 red.v4 per phase. (R11 kernel, measured ~24.5us.)
// ---------------------------------------------------------------------------
__global__ __launch_bounds__(256) void edge_agg_kernel(
    const float* __restrict__ nte_tab,
    const int* __restrict__ input_nodes,
    const int* __restrict__ edge_src,
    const int* __restrict__ edge_dst) {
    const int lane = threadIdx.x & 31;
    const int gw   = blockIdx.x * 8 + (threadIdx.x >> 5);   // global warp id
    const int base = gw * 32;                               // first edge (flat)
    const int t    = base >> 18;                            // E = 2^18

    const int src  = __ldg(&edge_src[base + lane]);
    const int dst  = __ldg(&edge_dst[base + lane]);
    const int row  = __ldg(&input_nodes[src]) * T + t;

    const int grp = lane >> 3;
    const int sub = lane & 7;

    #pragma unroll
    for (int p = 0; p < 8; p++) {
        const int j    = 4 * p + grp;
        const int rowj = __shfl_sync(0xFFFFFFFFu, row, j);
        const int dstj = __shfl_sync(0xFFFFFFFFu, dst, j);

        const float4 v = __ldg((const float4*)nte_tab + (size_t)rowj * (U / 4) + sub);
        float* pdst = g_agg + ((size_t)dstj * T + t) * U + sub * 4;
        asm volatile("red.global.add.v4.f32 [%0], {%1,%2,%3,%4};"
                     :: "l"(pdst), "f"(v.x), "f"(v.y), "f"(v.z), "f"(v.w) : "memory");
    }
}

// ---------------------------------------------------------------------------
// Kernel 2: finalize (R7 version, measured 22.8us) + out_nodes prefetch.
// BB=16 rows/block, 256 threads, warp w: t = w&3, rows (w>>2)*8..+7.
// ---------------------------------------------------------------------------
__global__ __launch_bounds__(256, 4) void finalize_kernel(
    const float* __restrict__ node_emb,
    const float* __restrict__ w,
    const float* __restrict__ ws1,
    const float* __restrict__ ws2,
    const int*  __restrict__ out_nodes,
    float*      __restrict__ out)
{
    __shared__ float nte_s[BB][T * U];
    __shared__ float scores_s[BB][T];
    __shared__ float att_s[BB][T];
    __shared__ float comb_s[BB][U];

    const int b0   = blockIdx.x * BB;
    const int tid  = threadIdx.x;
    const int lane = tid & 31;
    const int warp = tid >> 5;
    const int t    = warp & 3;
    const int bbase = (warp >> 2) * 8;

    {
        const float4* s4 = (const float4*)(g_agg + (size_t)b0 * T * U);
        float4* d4 = (float4*)&nte_s[0][0];
        #pragma unroll
        for (int i = tid; i < BB * T * U / 4; i += 256) d4[i] = s4[i];
    }
    // Prefetch out_nodes: lane r (r<8) keeps row (bbase+r)'s node index.
    const int nidx_mine = __ldg(&out_nodes[b0 + bbase + (lane & 7)]);
    __syncthreads();

    {
        float w1r[U];
        #pragma unroll
        for (int u = 0; u < U; u++) w1r[u] = __ldg(&ws1[(t * U + u) * A + lane]);
        const float w2r = __ldg(&ws2[t * A + lane]);

        #pragma unroll
        for (int i = 0; i < 8; i++) {
            const int bb = bbase + i;
            float acc = 0.f;
            #pragma unroll
            for (int u = 0; u < U; u++) acc += nte_s[bb][t * U + u] * w1r[u];
            float sc = tanhf(acc) * w2r;
            #pragma unroll
            for (int o = 16; o; o >>= 1) sc += __shfl_xor_sync(0xFFFFFFFFu, sc, o);
            if (lane == 0) scores_s[bb][t] = sc;
        }
    }
    __syncthreads();

    if (tid < BB) {
        float s0 = scores_s[tid][0], s1 = scores_s[tid][1];
        float s2 = scores_s[tid][2], s3 = scores_s[tid][3];
        float m = fmaxf(fmaxf(s0, s1), fmaxf(s2, s3));
        float e0 = __expf(s0 - m), e1 = __expf(s1 - m);
        float e2 = __expf(s2 - m), e3 = __expf(s3 - m);
        float inv = 1.f / (e0 + e1 + e2 + e3);
        att_s[tid][0] = e0 * inv; att_s[tid][1] = e1 * inv;
        att_s[tid][2] = e2 * inv; att_s[tid][3] = e3 * inv;
    }
    __syncthreads();

    #pragma unroll
    for (int i = tid; i < BB * U; i += 256) {
        const int bb = i >> 5, u = i & 31;
        float c = 0.f;
        #pragma unroll
        for (int tt = 0; tt < T; tt++) c += att_s[bb][tt] * nte_s[bb][tt * U + u];
        comb_s[bb][u] = c;
    }
    __syncthreads();

    ull acc[8][2];
    #pragma unroll
    for (int i = 0; i < 8; i++) { acc[i][0] = 0; acc[i][1] = 0; }

    const float4* wbase = (const float4*)w + (size_t)t * U * (D / 4) + lane;
    #pragma unroll
    for (int uc = 0; uc < U; uc += 4) {
        ull wlo[4], whi[4];
        #pragma unroll
        for (int j = 0; j < 4; j++) {
            const float4 wv = __ldg(&wbase[(uc + j) * (D / 4)]);
            PACK_F32X2(wlo[j], wv.x, wv.y);
            PACK_F32X2(whi[j], wv.z, wv.w);
        }
        #pragma unroll
        for (int i = 0; i < 8; i++) {
            const int bb = bbase + i;
            const float4 cb = ((const float4*)&comb_s[bb][0])[uc >> 2];
            ull c2;
            PACK_DUP_F32X2(c2, cb.x);
            FMA_F32X2(acc[i][0], c2, wlo[0], acc[i][0]);
            FMA_F32X2(acc[i][1], c2, whi[0], acc[i][1]);
            PACK_DUP_F32X2(c2, cb.y);
            FMA_F32X2(acc[i][0], c2, wlo[1], acc[i][0]);
            FMA_F32X2(acc[i][1], c2, whi[1], acc[i][1]);
            PACK_DUP_F32X2(c2, cb.z);
            FMA_F32X2(acc[i][0], c2, wlo[2], acc[i][0]);
            FMA_F32X2(acc[i][1], c2, whi[2], acc[i][1]);
            PACK_DUP_F32X2(c2, cb.w);
            FMA_F32X2(acc[i][0], c2, wlo[3], acc[i][0]);
            FMA_F32X2(acc[i][1], c2, whi[3], acc[i][1]);
        }
    }

    #pragma unroll
    for (int i = 0; i < 8; i++) {
        const int bb = bbase + i;
        const int b  = b0 + bb;
        const int nidx = __shfl_sync(0xFFFFFFFFu, nidx_mine, i);

        float4 o;
        UNPACK_F32X2(o.x, o.y, acc[i][0]);
        UNPACK_F32X2(o.z, o.w, acc[i][1]);

        const float4 nv = __ldg((const float4*)node_emb + (size_t)nidx * (D / 4) + lane);
        o.x += nv.x; o.y += nv.y; o.z += nv.z; o.w += nv.w;

        float ss = o.x * o.x + o.y * o.y + o.z * o.z + o.w * o.w;
        #pragma unroll
        for (int off = 16; off; off >>= 1) ss += __shfl_xor_sync(0xFFFFFFFFu, ss, off);

        const float scale = 1.f / fmaxf(sqrtf(ss), 1e-12f);
        o.x *= scale; o.y *= scale; o.z *= scale; o.w *= scale;

        ((float4*)out)[(size_t)(b * T + t) * (D / 4) + lane] = o;
    }
}

// ---------------------------------------------------------------------------
// Launch
// ---------------------------------------------------------------------------
extern "C" void kernel_launch(void* const* d_in, const int* in_sizes, int n_in,
                              void* d_out, int out_size) {
    const float* node_emb     = (const float*)d_in[0];
    const float* nte_tab      = (const float*)d_in[1];
    const float* trans_w      = (const float*)d_in[2];
    const float* trans_w_s1   = (const float*)d_in[3];
    const float* trans_w_s2   = (const float*)d_in[4];
    const int*   input_nodes  = (const int*)d_in[5];
    const int*   output_nodes = (const int*)d_in[6];
    const int*   edge_src     = (const int*)d_in[7];
    const int*   edge_dst     = (const int*)d_in[8];
    float*       out          = (float*)d_out;

    void* agg_ptr = nullptr;
    cudaGetSymbolAddress(&agg_ptr, g_agg);
    cudaMemsetAsync(agg_ptr, 0, (size_t)B * T * U * sizeof(float));

    edge_agg_kernel<<<(T * E) / 256, 256>>>(nte_tab, input_nodes, edge_src, edge_dst);

    finalize_kernel<<<B / BB, 256>>>(node_emb, trans_w, trans_w_s1, trans_w_s2,
                                     output_nodes, out);
}

// round 13
// speedup vs baseline: 1.2806x; 1.0006x over previous
#include <cuda_runtime.h>
#include <cstdint>

#define NUM_NODES 500000
#define D 128
#define U 32
#define T 4
#define A 32
#define N_SRC 65536
#define B 8192
#define E 262144
#define BB 16  // batch rows per finalize block

typedef unsigned long long ull;

#define FMA_F32X2(d, a, b, c) \
    asm("fma.rn.f32x2 %0, %1, %2, %3;" : "=l"(d) : "l"(a), "l"(b), "l"(c))
#define PACK_DUP_F32X2(d, s) \
    asm("mov.b64 %0, {%1, %1};" : "=l"(d) : "f"(s))
#define PACK_F32X2(d, lo, hi) \
    asm("mov.b64 %0, {%1, %2};" : "=l"(d) : "f"(lo), "f"(hi))
#define UNPACK_F32X2(lo, hi, s) \
    asm("mov.b64 {%0, %1}, %2;" : "=f"(lo), "=f"(hi) : "l"(s))

// Scratch accumulator: agg[b][t][u]  (4 MB)
__device__ float g_agg[B * T * U];

// ---------------------------------------------------------------------------
// Kernel 1: edge aggregation (push, red.v4), shfl-distributed indices.
// Triggers dependent-launch release at block start (PDL).
// ---------------------------------------------------------------------------
__global__ __launch_bounds__(256) void edge_agg_kernel(
    const float* __restrict__ nte_tab,
    const int* __restrict__ input_nodes,
    const int* __restrict__ edge_src,
    const int* __restrict__ edge_dst) {
    cudaTriggerProgrammaticLaunchCompletion();

    const int lane = threadIdx.x & 31;
    const int gw   = blockIdx.x * 8 + (threadIdx.x >> 5);
    const int base = gw * 32;
    const int t    = base >> 18;                            // E = 2^18

    const int src  = __ldg(&edge_src[base + lane]);
    const int dst  = __ldg(&edge_dst[base + lane]);
    const int row  = __ldg(&input_nodes[src]) * T + t;

    const int grp = lane >> 3;
    const int sub = lane & 7;

    #pragma unroll
    for (int p = 0; p < 8; p++) {
        const int j    = 4 * p + grp;
        const int rowj = __shfl_sync(0xFFFFFFFFu, row, j);
        const int dstj = __shfl_sync(0xFFFFFFFFu, dst, j);

        const float4 v = __ldg((const float4*)nte_tab + (size_t)rowj * (U / 4) + sub);
        float* pdst = g_agg + ((size_t)dstj * T + t) * U + sub * 4;
        asm volatile("red.global.add.v4.f32 [%0], {%1,%2,%3,%4};"
                     :: "l"(pdst), "f"(v.x), "f"(v.y), "f"(v.z), "f"(v.w) : "memory");
    }
}

// ---------------------------------------------------------------------------
// Kernel 2: finalize. Independent prologue (node_emb gather -> smem) runs
// BEFORE the grid-dependency wait; g_agg is touched only after it.
// ---------------------------------------------------------------------------
__global__ __launch_bounds__(256, 4) void finalize_kernel(
    const float* __restrict__ node_emb,
    const float* __restrict__ w,
    const float* __restrict__ ws1,
    const float* __restrict__ ws2,
    const int*  __restrict__ out_nodes,
    float*      __restrict__ out)
{
    __shared__ float4 nv_s[BB][D / 4];      // 8 KB: prefetched node_emb rows
    __shared__ float  nte_s[BB][T * U];     // 8 KB
    __shared__ float  scores_s[BB][T];
    __shared__ float  att_s[BB][T];
    __shared__ float  comb_s[BB][U];

    const int b0   = blockIdx.x * BB;
    const int tid  = threadIdx.x;
    const int lane = tid & 31;
    const int warp = tid >> 5;
    const int t    = warp & 3;
    const int bbase = (warp >> 2) * 8;

    // ---- independent prologue: gather node_emb rows into smem ----
    #pragma unroll
    for (int i = tid; i < BB * (D / 4); i += 256) {
        const int r = i >> 5, slot = i & 31;
        const int nidx = __ldg(&out_nodes[b0 + r]);
        nv_s[r][slot] = __ldg((const float4*)node_emb + (size_t)nidx * (D / 4) + slot);
    }

    // ---- wait for edge_agg's g_agg writes (PDL; no-op if launched serial) ----
    cudaGridDependencySynchronize();

    {
        const float4* s4 = (const float4*)(g_agg + (size_t)b0 * T * U);
        float4* d4 = (float4*)&nte_s[0][0];
        #pragma unroll
        for (int i = tid; i < BB * T * U / 4; i += 256) d4[i] = s4[i];
    }
    __syncthreads();

    {
        float w1r[U];
        #pragma unroll
        for (int u = 0; u < U; u++) w1r[u] = __ldg(&ws1[(t * U + u) * A + lane]);
        const float w2r = __ldg(&ws2[t * A + lane]);

        #pragma unroll
        for (int i = 0; i < 8; i++) {
            const int bb = bbase + i;
            float acc = 0.f;
            #pragma unroll
            for (int u = 0; u < U; u++) acc += nte_s[bb][t * U + u] * w1r[u];
            float sc = tanhf(acc) * w2r;
            #pragma unroll
            for (int o = 16; o; o >>= 1) sc += __shfl_xor_sync(0xFFFFFFFFu, sc, o);
            if (lane == 0) scores_s[bb][t] = sc;
        }
    }
    __syncthreads();

    if (tid < BB) {
        float s0 = scores_s[tid][0], s1 = scores_s[tid][1];
        float s2 = scores_s[tid][2], s3 = scores_s[tid][3];
        float m = fmaxf(fmaxf(s0, s1), fmaxf(s2, s3));
        float e0 = __expf(s0 - m), e1 = __expf(s1 - m);
        float e2 = __expf(s2 - m), e3 = __expf(s3 - m);
        float inv = 1.f / (e0 + e1 + e2 + e3);
        att_s[tid][0] = e0 * inv; att_s[tid][1] = e1 * inv;
        att_s[tid][2] = e2 * inv; att_s[tid][3] = e3 * inv;
    }
    __syncthreads();

    #pragma unroll
    for (int i = tid; i < BB * U; i += 256) {
        const int bb = i >> 5, u = i & 31;
        float c = 0.f;
        #pragma unroll
        for (int tt = 0; tt < T; tt++) c += att_s[bb][tt] * nte_s[bb][tt * U + u];
        comb_s[bb][u] = c;
    }
    __syncthreads();

    ull acc[8][2];
    #pragma unroll
    for (int i = 0; i < 8; i++) { acc[i][0] = 0; acc[i][1] = 0; }

    const float4* wbase = (const float4*)w + (size_t)t * U * (D / 4) + lane;
    #pragma unroll
    for (int uc = 0; uc < U; uc += 4) {
        ull wlo[4], whi[4];
        #pragma unroll
        for (int j = 0; j < 4; j++) {
            const float4 wv = __ldg(&wbase[(uc + j) * (D / 4)]);
            PACK_F32X2(wlo[j], wv.x, wv.y);
            PACK_F32X2(whi[j], wv.z, wv.w);
        }
        #pragma unroll
        for (int i = 0; i < 8; i++) {
            const int bb = bbase + i;
            const float4 cb = ((const float4*)&comb_s[bb][0])[uc >> 2];
            ull c2;
            PACK_DUP_F32X2(c2, cb.x);
            FMA_F32X2(acc[i][0], c2, wlo[0], acc[i][0]);
            FMA_F32X2(acc[i][1], c2, whi[0], acc[i][1]);
            PACK_DUP_F32X2(c2, cb.y);
            FMA_F32X2(acc[i][0], c2, wlo[1], acc[i][0]);
            FMA_F32X2(acc[i][1], c2, whi[1], acc[i][1]);
            PACK_DUP_F32X2(c2, cb.z);
            FMA_F32X2(acc[i][0], c2, wlo[2], acc[i][0]);
            FMA_F32X2(acc[i][1], c2, whi[2], acc[i][1]);
            PACK_DUP_F32X2(c2, cb.w);
            FMA_F32X2(acc[i][0], c2, wlo[3], acc[i][0]);
            FMA_F32X2(acc[i][1], c2, whi[3], acc[i][1]);
        }
    }

    #pragma unroll
    for (int i = 0; i < 8; i++) {
        const int bb = bbase + i;
        const int b  = b0 + bb;

        float4 o;
        UNPACK_F32X2(o.x, o.y, acc[i][0]);
        UNPACK_F32X2(o.z, o.w, acc[i][1]);

        const float4 nv = nv_s[bb][lane];   // prefetched (smem)
        o.x += nv.x; o.y += nv.y; o.z += nv.z; o.w += nv.w;

        float ss = o.x * o.x + o.y * o.y + o.z * o.z + o.w * o.w;
        #pragma unroll
        for (int off = 16; off; off >>= 1) ss += __shfl_xor_sync(0xFFFFFFFFu, ss, off);

        const float scale = 1.f / fmaxf(sqrtf(ss), 1e-12f);
        o.x *= scale; o.y *= scale; o.z *= scale; o.w *= scale;

        ((float4*)out)[(size_t)(b * T + t) * (D / 4) + lane] = o;
    }
}

// ---------------------------------------------------------------------------
// Launch
// ---------------------------------------------------------------------------
extern "C" void kernel_launch(void* const* d_in, const int* in_sizes, int n_in,
                              void* d_out, int out_size) {
    const float* node_emb     = (const float*)d_in[0];
    const float* nte_tab      = (const float*)d_in[1];
    const float* trans_w      = (const float*)d_in[2];
    const float* trans_w_s1   = (const float*)d_in[3];
    const float* trans_w_s2   = (const float*)d_in[4];
    const int*   input_nodes  = (const int*)d_in[5];
    const int*   output_nodes = (const int*)d_in[6];
    const int*   edge_src     = (const int*)d_in[7];
    const int*   edge_dst     = (const int*)d_in[8];
    float*       out          = (float*)d_out;

    void* agg_ptr = nullptr;
    cudaGetSymbolAddress(&agg_ptr, g_agg);
    cudaMemsetAsync(agg_ptr, 0, (size_t)B * T * U * sizeof(float));

    edge_agg_kernel<<<(T * E) / 256, 256>>>(nte_tab, input_nodes, edge_src, edge_dst);

    // finalize with Programmatic Stream Serialization (PDL)
    cudaLaunchConfig_t cfg = {};
    cfg.gridDim  = dim3(B / BB, 1, 1);
    cfg.blockDim = dim3(256, 1, 1);
    cfg.dynamicSmemBytes = 0;
    cfg.stream = 0;
    cudaLaunchAttribute attrs[1];
    attrs[0].id = cudaLaunchAttributeProgrammaticStreamSerialization;
    attrs[0].val.programmaticStreamSerializationAllowed = 1;
    cfg.attrs = attrs;
    cfg.numAttrs = 1;
    cudaLaunchKernelEx(&cfg, finalize_kernel,
                       node_emb, trans_w, trans_w_s1, trans_w_s2,
                       output_nodes, out);
}

// round 14
// speedup vs baseline: 1.3331x; 1.0410x over previous
#include <cuda_runtime.h>
#include <cstdint>

#define NUM_NODES 500000
#define D 128
#define U 32
#define T 4
#define A 32
#define N_SRC 65536
#define B 8192
#define E 262144
#define BB 16  // batch rows per finalize block

typedef unsigned long long ull;

#define FMA_F32X2(d, a, b, c) \
    asm("fma.rn.f32x2 %0, %1, %2, %3;" : "=l"(d) : "l"(a), "l"(b), "l"(c))
#define PACK_DUP_F32X2(d, s) \
    asm("mov.b64 %0, {%1, %1};" : "=l"(d) : "f"(s))
#define PACK_F32X2(d, lo, hi) \
    asm("mov.b64 %0, {%1, %2};" : "=l"(d) : "f"(lo), "f"(hi))
#define UNPACK_F32X2(lo, hi, s) \
    asm("mov.b64 {%0, %1}, %2;" : "=f"(lo), "=f"(hi) : "l"(s))

// Scratch accumulator: agg[b][t][u] (4 MB).
// INVARIANT: zero at kernel_launch entry. Statically zero-initialized at
// module load; finalize_kernel re-zeroes each slice after consuming it,
// so every subsequent graph replay also starts from zero. No memset needed.
__device__ float g_agg[B * T * U];

// ---------------------------------------------------------------------------
// Kernel 1: edge aggregation (push, red.v4), shfl-distributed indices.
// One warp = 32 edges; indices loaded once per lane, broadcast via shfl.
// ---------------------------------------------------------------------------
__global__ __launch_bounds__(256) void edge_agg_kernel(
    const float* __restrict__ nte_tab,
    const int* __restrict__ input_nodes,
    const int* __restrict__ edge_src,
    const int* __restrict__ edge_dst) {
    cudaTriggerProgrammaticLaunchCompletion();

    const int lane = threadIdx.x & 31;
    const int gw   = blockIdx.x * 8 + (threadIdx.x >> 5);
    const int base = gw * 32;
    const int t    = base >> 18;                            // E = 2^18

    const int src  = __ldg(&edge_src[base + lane]);
    const int dst  = __ldg(&edge_dst[base + lane]);
    const int row  = __ldg(&input_nodes[src]) * T + t;

    const int grp = lane >> 3;
    const int sub = lane & 7;

    #pragma unroll
    for (int p = 0; p < 8; p++) {
        const int j    = 4 * p + grp;
        const int rowj = __shfl_sync(0xFFFFFFFFu, row, j);
        const int dstj = __shfl_sync(0xFFFFFFFFu, dst, j);

        const float4 v = __ldg((const float4*)nte_tab + (size_t)rowj * (U / 4) + sub);
        float* pdst = g_agg + ((size_t)dstj * T + t) * U + sub * 4;
        asm volatile("red.global.add.v4.f32 [%0], {%1,%2,%3,%4};"
                     :: "l"(pdst), "f"(v.x), "f"(v.y), "f"(v.z), "f"(v.w) : "memory");
    }
}

// ---------------------------------------------------------------------------
// Kernel 2: finalize. Independent prologue (node_emb gather -> smem) before
// the PDL wait; consumes g_agg then zeroes its slice for the next replay.
// ---------------------------------------------------------------------------
__global__ __launch_bounds__(256, 4) void finalize_kernel(
    const float* __restrict__ node_emb,
    const float* __restrict__ w,
    const float* __restrict__ ws1,
    const float* __restrict__ ws2,
    const int*  __restrict__ out_nodes,
    float*      __restrict__ out)
{
    __shared__ float4 nv_s[BB][D / 4];      // 8 KB: prefetched node_emb rows
    __shared__ float  nte_s[BB][T * U];     // 8 KB
    __shared__ float  scores_s[BB][T];
    __shared__ float  att_s[BB][T];
    __shared__ float  comb_s[BB][U];

    const int b0   = blockIdx.x * BB;
    const int tid  = threadIdx.x;
    const int lane = tid & 31;
    const int warp = tid >> 5;
    const int t    = warp & 3;
    const int bbase = (warp >> 2) * 8;

    // ---- independent prologue: gather node_emb rows into smem ----
    #pragma unroll
    for (int i = tid; i < BB * (D / 4); i += 256) {
        const int r = i >> 5, slot = i & 31;
        const int nidx = __ldg(&out_nodes[b0 + r]);
        nv_s[r][slot] = __ldg((const float4*)node_emb + (size_t)nidx * (D / 4) + slot);
    }

    // ---- wait for edge_agg's g_agg writes (PDL) ----
    cudaGridDependencySynchronize();

    {
        const float4* s4 = (const float4*)(g_agg + (size_t)b0 * T * U);
        float4* d4 = (float4*)&nte_s[0][0];
        #pragma unroll
        for (int i = tid; i < BB * T * U / 4; i += 256) d4[i] = s4[i];
    }
    __syncthreads();

    // Re-zero this block's g_agg slice for the next graph replay
    // (reads above are complete past the barrier).
    {
        float4* z4 = (float4*)(g_agg + (size_t)b0 * T * U);
        const float4 zero = make_float4(0.f, 0.f, 0.f, 0.f);
        #pragma unroll
        for (int i = tid; i < BB * T * U / 4; i += 256) z4[i] = zero;
    }

    {
        float w1r[U];
        #pragma unroll
        for (int u = 0; u < U; u++) w1r[u] = __ldg(&ws1[(t * U + u) * A + lane]);
        const float w2r = __ldg(&ws2[t * A + lane]);

        #pragma unroll
        for (int i = 0; i < 8; i++) {
            const int bb = bbase + i;
            float acc = 0.f;
            #pragma unroll
            for (int u = 0; u < U; u++) acc += nte_s[bb][t * U + u] * w1r[u];
            float sc = tanhf(acc) * w2r;
            #pragma unroll
            for (int o = 16; o; o >>= 1) sc += __shfl_xor_sync(0xFFFFFFFFu, sc, o);
            if (lane == 0) scores_s[bb][t] = sc;
        }
    }
    __syncthreads();

    if (tid < BB) {
        float s0 = scores_s[tid][0], s1 = scores_s[tid][1];
        float s2 = scores_s[tid][2], s3 = scores_s[tid][3];
        float m = fmaxf(fmaxf(s0, s1), fmaxf(s2, s3));
        float e0 = __expf(s0 - m), e1 = __expf(s1 - m);
        float e2 = __expf(s2 - m), e3 = __expf(s3 - m);
        float inv = 1.f / (e0 + e1 + e2 + e3);
        att_s[tid][0] = e0 * inv; att_s[tid][1] = e1 * inv;
        att_s[tid][2] = e2 * inv; att_s[tid][3] = e3 * inv;
    }
    __syncthreads();

    #pragma unroll
    for (int i = tid; i < BB * U; i += 256) {
        const int bb = i >> 5, u = i & 31;
        float c = 0.f;
        #pragma unroll
        for (int tt = 0; tt < T; tt++) c += att_s[bb][tt] * nte_s[bb][tt * U + u];
        comb_s[bb][u] = c;
    }
    __syncthreads();

    ull acc[8][2];
    #pragma unroll
    for (int i = 0; i < 8; i++) { acc[i][0] = 0; acc[i][1] = 0; }

    const float4* wbase = (const float4*)w + (size_t)t * U * (D / 4) + lane;
    #pragma unroll
    for (int uc = 0; uc < U; uc += 4) {
        ull wlo[4], whi[4];
        #pragma unroll
        for (int j = 0; j < 4; j++) {
            const float4 wv = __ldg(&wbase[(uc + j) * (D / 4)]);
            PACK_F32X2(wlo[j], wv.x, wv.y);
            PACK_F32X2(whi[j], wv.z, wv.w);
        }
        #pragma unroll
        for (int i = 0; i < 8; i++) {
            const int bb = bbase + i;
            const float4 cb = ((const float4*)&comb_s[bb][0])[uc >> 2];
            ull c2;
            PACK_DUP_F32X2(c2, cb.x);
            FMA_F32X2(acc[i][0], c2, wlo[0], acc[i][0]);
            FMA_F32X2(acc[i][1], c2, whi[0], acc[i][1]);
            PACK_DUP_F32X2(c2, cb.y);
            FMA_F32X2(acc[i][0], c2, wlo[1], acc[i][0]);
            FMA_F32X2(acc[i][1], c2, whi[1], acc[i][1]);
            PACK_DUP_F32X2(c2, cb.z);
            FMA_F32X2(acc[i][0], c2, wlo[2], acc[i][0]);
            FMA_F32X2(acc[i][1], c2, whi[2], acc[i][1]);
            PACK_DUP_F32X2(c2, cb.w);
            FMA_F32X2(acc[i][0], c2, wlo[3], acc[i][0]);
            FMA_F32X2(acc[i][1], c2, whi[3], acc[i][1]);
        }
    }

    #pragma unroll
    for (int i = 0; i < 8; i++) {
        const int bb = bbase + i;
        const int b  = b0 + bb;

        float4 o;
        UNPACK_F32X2(o.x, o.y, acc[i][0]);
        UNPACK_F32X2(o.z, o.w, acc[i][1]);

        const float4 nv = nv_s[bb][lane];
        o.x += nv.x; o.y += nv.y; o.z += nv.z; o.w += nv.w;

        float ss = o.x * o.x + o.y * o.y + o.z * o.z + o.w * o.w;
        #pragma unroll
        for (int off = 16; off; off >>= 1) ss += __shfl_xor_sync(0xFFFFFFFFu, ss, off);

        const float scale = 1.f / fmaxf(sqrtf(ss), 1e-12f);
        o.x *= scale; o.y *= scale; o.z *= scale; o.w *= scale;

        ((float4*)out)[(size_t)(b * T + t) * (D / 4) + lane] = o;
    }
}

// ---------------------------------------------------------------------------
// Launch — two nodes only (no memset).
// ---------------------------------------------------------------------------
extern "C" void kernel_launch(void* const* d_in, const int* in_sizes, int n_in,
                              void* d_out, int out_size) {
    const float* node_emb     = (const float*)d_in[0];
    const float* nte_tab      = (const float*)d_in[1];
    const float* trans_w      = (const float*)d_in[2];
    const float* trans_w_s1   = (const float*)d_in[3];
    const float* trans_w_s2   = (const float*)d_in[4];
    const int*   input_nodes  = (const int*)d_in[5];
    const int*   output_nodes = (const int*)d_in[6];
    const int*   edge_src     = (const int*)d_in[7];
    const int*   edge_dst     = (const int*)d_in[8];
    float*       out          = (float*)d_out;

    edge_agg_kernel<<<(T * E) / 256, 256>>>(nte_tab, input_nodes, edge_src, edge_dst);

    // finalize with Programmatic Stream Serialization (PDL)
    cudaLaunchConfig_t cfg = {};
    cfg.gridDim  = dim3(B / BB, 1, 1);
    cfg.blockDim = dim3(256, 1, 1);
    cfg.dynamicSmemBytes = 0;
    cfg.stream = 0;
    cudaLaunchAttribute attrs[1];
    attrs[0].id = cudaLaunchAttributeProgrammaticStreamSerialization;
    attrs[0].val.programmaticStreamSerializationAllowed = 1;
    cfg.attrs = attrs;
    cfg.numAttrs = 1;
    cudaLaunchKernelEx(&cfg, finalize_kernel,
                       node_emb, trans_w, trans_w_s1, trans_w_s2,
                       output_nodes, out);
}

// round 16
// speedup vs baseline: 1.3920x; 1.0442x over previous
#include <cuda_runtime.h>
#include <cstdint>

#define NUM_NODES 500000
#define D 128
#define U 32
#define T 4
#define A 32
#define N_SRC 65536
#define B 8192
#define E 262144
#define BB 16  // batch rows per finalize block

typedef unsigned long long ull;

#define FMA_F32X2(d, a, b, c) \
    asm("fma.rn.f32x2 %0, %1, %2, %3;" : "=l"(d) : "l"(a), "l"(b), "l"(c))
#define PACK_DUP_F32X2(d, s) \
    asm("mov.b64 %0, {%1, %1};" : "=l"(d) : "f"(s))
#define PACK_F32X2(d, lo, hi) \
    asm("mov.b64 %0, {%1, %2};" : "=l"(d) : "f"(lo), "f"(hi))
#define UNPACK_F32X2(lo, hi, s) \
    asm("mov.b64 {%0, %1}, %2;" : "=f"(lo), "=f"(hi) : "l"(s))

// Scratch accumulator: agg[b][t][u] (4 MB).
// INVARIANT: zero at kernel_launch entry. Statically zero-initialized at
// module load; finalize_kernel re-zeroes each slice after consuming it,
// so every graph replay also starts from zero. No memset node needed.
__device__ float g_agg[B * T * U];

// ---------------------------------------------------------------------------
// Kernel 1: edge aggregation (push, red.v4), shfl-distributed indices.
// One warp = 32 edges; indices loaded once per lane, broadcast via shfl.
// ---------------------------------------------------------------------------
__global__ __launch_bounds__(256) void edge_agg_kernel(
    const float* __restrict__ nte_tab,
    const int* __restrict__ input_nodes,
    const int* __restrict__ edge_src,
    const int* __restrict__ edge_dst) {
    cudaTriggerProgrammaticLaunchCompletion();

    const int lane = threadIdx.x & 31;
    const int gw   = blockIdx.x * 8 + (threadIdx.x >> 5);
    const int base = gw * 32;
    const int t    = base >> 18;                            // E = 2^18

    const int src  = __ldg(&edge_src[base + lane]);
    const int dst  = __ldg(&edge_dst[base + lane]);
    const int row  = __ldg(&input_nodes[src]) * T + t;

    const int grp = lane >> 3;
    const int sub = lane & 7;

    #pragma unroll
    for (int p = 0; p < 8; p++) {
        const int j    = 4 * p + grp;
        const int rowj = __shfl_sync(0xFFFFFFFFu, row, j);
        const int dstj = __shfl_sync(0xFFFFFFFFu, dst, j);

        const float4 v = __ldg((const float4*)nte_tab + (size_t)rowj * (U / 4) + sub);
        float* pdst = g_agg + ((size_t)dstj * T + t) * U + sub * 4;
        asm volatile("red.global.add.v4.f32 [%0], {%1,%2,%3,%4};"
                     :: "l"(pdst), "f"(v.x), "f"(v.y), "f"(v.z), "f"(v.w) : "memory");
    }
}

// ---------------------------------------------------------------------------
// Kernel 2: finalize. Prologue (node_emb gather + ALL stage-A weights) runs
// before the PDL wait. 3 barriers: nte-load / scores / combine.
// ---------------------------------------------------------------------------
__global__ __launch_bounds__(256, 4) void finalize_kernel(
    const float* __restrict__ node_emb,
    const float* __restrict__ w,
    const float* __restrict__ ws1,
    const float* __restrict__ ws2,
    const int*  __restrict__ out_nodes,
    float*      __restrict__ out)
{
    __shared__ float4 nv_s[BB][D / 4];      // 8 KB: prefetched node_emb rows
    __shared__ float  nte_s[BB][T * U];     // 8 KB
    __shared__ float  scores_s[BB][T];
    __shared__ float  comb_s[BB][U];

    const int b0   = blockIdx.x * BB;
    const int tid  = threadIdx.x;
    const int lane = tid & 31;
    const int warp = tid >> 5;
    const int t    = warp & 3;
    const int bbase = (warp >> 2) * 8;

    // ---- independent prologue (overlaps edge_agg tail via PDL) ----
    // node_emb gathers -> smem
    #pragma unroll
    for (int i = tid; i < BB * (D / 4); i += 256) {
        const int r = i >> 5, slot = i & 31;
        const int nidx = __ldg(&out_nodes[b0 + r]);
        nv_s[r][slot] = __ldg((const float4*)node_emb + (size_t)nidx * (D / 4) + slot);
    }
    // stage-A weights -> registers (independent of g_agg)
    float w1r[U];
    #pragma unroll
    for (int u = 0; u < U; u++) w1r[u] = __ldg(&ws1[(t * U + u) * A + lane]);
    const float w2r = __ldg(&ws2[t * A + lane]);

    // ---- wait for edge_agg's g_agg writes (PDL) ----
    cudaGridDependencySynchronize();

    {
        const float4* s4 = (const float4*)(g_agg + (size_t)b0 * T * U);
        float4* d4 = (float4*)&nte_s[0][0];
        #pragma unroll
        for (int i = tid; i < BB * T * U / 4; i += 256) d4[i] = s4[i];
    }
    __syncthreads();                                    // barrier 1

    // Re-zero this block's g_agg slice for the next graph replay.
    {
        float4* z4 = (float4*)(g_agg + (size_t)b0 * T * U);
        const float4 zero = make_float4(0.f, 0.f, 0.f, 0.f);
        #pragma unroll
        for (int i = tid; i < BB * T * U / 4; i += 256) z4[i] = zero;
    }

    // Stage A: warp (t, half) computes scores for its 8 rows.
    #pragma unroll
    for (int i = 0; i < 8; i++) {
        const int bb = bbase + i;
        float acc = 0.f;
        #pragma unroll
        for (int u = 0; u < U; u++) acc += nte_s[bb][t * U + u] * w1r[u];
        float sc = tanhf(acc) * w2r;
        #pragma unroll
        for (int o = 16; o; o >>= 1) sc += __shfl_xor_sync(0xFFFFFFFFu, sc, o);
        if (lane == 0) scores_s[bb][t] = sc;
    }
    __syncthreads();                                    // barrier 2

    // Combine with inline softmax (no separate softmax phase/barrier).
    #pragma unroll
    for (int i = tid; i < BB * U; i += 256) {
        const int bb = i >> 5, u = i & 31;
        const float s0 = scores_s[bb][0], s1 = scores_s[bb][1];
        const float s2 = scores_s[bb][2], s3 = scores_s[bb][3];
        const float m  = fmaxf(fmaxf(s0, s1), fmaxf(s2, s3));
        const float e0 = __expf(s0 - m), e1 = __expf(s1 - m);
        const float e2 = __expf(s2 - m), e3 = __expf(s3 - m);
        const float inv = 1.f / (e0 + e1 + e2 + e3);
        comb_s[bb][u] = (e0 * nte_s[bb][0 * U + u] + e1 * nte_s[bb][1 * U + u] +
                         e2 * nte_s[bb][2 * U + u] + e3 * nte_s[bb][3 * U + u]) * inv;
    }
    __syncthreads();                                    // barrier 3

    // Stage B: acc[r] = comb[r] @ w[t]; f32x2 FMAs, LDS.128 comb reads.
    ull acc[8][2];
    #pragma unroll
    for (int i = 0; i < 8; i++) { acc[i][0] = 0; acc[i][1] = 0; }

    const float4* wbase = (const float4*)w + (size_t)t * U * (D / 4) + lane;
    #pragma unroll
    for (int uc = 0; uc < U; uc += 4) {
        ull wlo[4], whi[4];
        #pragma unroll
        for (int j = 0; j < 4; j++) {
            const float4 wv = __ldg(&wbase[(uc + j) * (D / 4)]);
            PACK_F32X2(wlo[j], wv.x, wv.y);
            PACK_F32X2(whi[j], wv.z, wv.w);
        }
        #pragma unroll
        for (int i = 0; i < 8; i++) {
            const int bb = bbase + i;
            const float4 cb = ((const float4*)&comb_s[bb][0])[uc >> 2];
            ull c2;
            PACK_DUP_F32X2(c2, cb.x);
            FMA_F32X2(acc[i][0], c2, wlo[0], acc[i][0]);
            FMA_F32X2(acc[i][1], c2, whi[0], acc[i][1]);
            PACK_DUP_F32X2(c2, cb.y);
            FMA_F32X2(acc[i][0], c2, wlo[1], acc[i][0]);
            FMA_F32X2(acc[i][1], c2, whi[1], acc[i][1]);
            PACK_DUP_F32X2(c2, cb.z);
            FMA_F32X2(acc[i][0], c2, wlo[2], acc[i][0]);
            FMA_F32X2(acc[i][1], c2, whi[2], acc[i][1]);
            PACK_DUP_F32X2(c2, cb.w);
            FMA_F32X2(acc[i][0], c2, wlo[3], acc[i][0]);
            FMA_F32X2(acc[i][1], c2, whi[3], acc[i][1]);
        }
    }

    #pragma unroll
    for (int i = 0; i < 8; i++) {
        const int bb = bbase + i;
        const int b  = b0 + bb;

        float4 o;
        UNPACK_F32X2(o.x, o.y, acc[i][0]);
        UNPACK_F32X2(o.z, o.w, acc[i][1]);

        const float4 nv = nv_s[bb][lane];
        o.x += nv.x; o.y += nv.y; o.z += nv.z; o.w += nv.w;

        float ss = o.x * o.x + o.y * o.y + o.z * o.z + o.w * o.w;
        #pragma unroll
        for (int off = 16; off; off >>= 1) ss += __shfl_xor_sync(0xFFFFFFFFu, ss, off);

        const float scale = 1.f / fmaxf(sqrtf(ss), 1e-12f);
        o.x *= scale; o.y *= scale; o.z *= scale; o.w *= scale;

        ((float4*)out)[(size_t)(b * T + t) * (D / 4) + lane] = o;
    }
}

// ---------------------------------------------------------------------------
// Launch — two nodes (edge + PDL finalize), no memset.
// ---------------------------------------------------------------------------
extern "C" void kernel_launch(void* const* d_in, const int* in_sizes, int n_in,
                              void* d_out, int out_size) {
    const float* node_emb     = (const float*)d_in[0];
    const float* nte_tab      = (const float*)d_in[1];
    const float* trans_w      = (const float*)d_in[2];
    const float* trans_w_s1   = (const float*)d_in[3];
    const float* trans_w_s2   = (const float*)d_in[4];
    const int*   input_nodes  = (const int*)d_in[5];
    const int*   output_nodes = (const int*)d_in[6];
    const int*   edge_src     = (const int*)d_in[7];
    const int*   edge_dst     = (const int*)d_in[8];
    float*       out          = (float*)d_out;

    edge_agg_kernel<<<(T * E) / 256, 256>>>(nte_tab, input_nodes, edge_src, edge_dst);

    cudaLaunchConfig_t cfg = {};
    cfg.gridDim  = dim3(B / BB, 1, 1);
    cfg.blockDim = dim3(256, 1, 1);
    cfg.dynamicSmemBytes = 0;
    cfg.stream = 0;
    cudaLaunchAttribute attrs[1];
    attrs[0].id = cudaLaunchAttributeProgrammaticStreamSerialization;
    attrs[0].val.programmaticStreamSerializationAllowed = 1;
    cfg.attrs = attrs;
    cfg.numAttrs = 1;
    cudaLaunchKernelEx(&cfg, finalize_kernel,
                       node_emb, trans_w, trans_w_s1, trans_w_s2,
                       output_nodes, out);
}